// round 13
// baseline (speedup 1.0000x reference)
#include <cuda_runtime.h>
#include <cuda_bf16.h>

// Output layout: [muTE (N floats)] ++ [M (N*N floats, row-major)]
// h = 0 (hunter), p = 1 (prey). N = 8192 for this problem.
//
// M is zero except rows/cols 0 and 1:
//   row 0: +v[j], row 1: -v[j], col 0: +v[i], col 1: -v[i], 2x2 corner special.
//   v[j] = mu[j]*(var01 - 2*mu0*mu1) + mu1*var[0,j] + mu0*var[1,j], v[0]=v[1]=0
//   (var[:,0] == var[0,:] bitwise since var = 0.5*(a + a^T)).
// muTE[0] = hp, muTE[1] = -hp, hp = var[0,1]; rest zero.
//
// TERMINAL FORM — evidence from rounds 1-12:
// Seven structurally distinct implementations (plain STG, __stcs, row-block,
// exact-grid, driver cudaMemsetAsync, memset+fixup, L2-resident-tail split)
// all drain the 268.5 MB output at ~7.2 TB/s store-issue / ~5.6 TB/s DRAM
// in 36.7-37.9 us; identical code re-runs span +-1.0 us (noise floor).
// Issue% varied 4.7-36.9 with no duration effect; cache policy inert; L2
// replay-residency falsified. Binding resource: HBM3e write-turnaround wall
// for a unique-address store stream; output bytes contractually fixed.

#define TPB 256u
#define VPT 4u   // float4 slots per thread; TPB*VPT divides total4 exactly

__device__ __forceinline__ void corner2x2(float mu0, float mu1,
                                          float var00, float var01, float var11,
                                          unsigned int row, float* x, float* y) {
    float hp = var01;
    float n3_pph = -2.f * mu1 * mu1 * mu0 + 2.f * mu1 * var01 + mu0 * var11;
    float n3_hhp = -2.f * mu0 * mu0 * mu1 + 2.f * mu0 * var01 + mu1 * var00;
    float n3_hpp = -2.f * mu0 * mu1 * mu1 + mu0 * var11 + 2.f * mu1 * var01;
    float chp = -n3_hhp + n3_hpp - hp;
    if (row == 0u) { *x = 2.f * n3_hhp + hp; *y = chp; }
    else           { *x = chp;               *y = -2.f * n3_pph + hp; }
}

__device__ __noinline__ float4 special_value(unsigned int off,
                                             const float* __restrict__ mu,
                                             const float* __restrict__ var,
                                             unsigned int N,
                                             unsigned int i,
                                             unsigned int j) {
    float4 r = make_float4(0.f, 0.f, 0.f, 0.f);

    if (off < N) {
        if (off == 0u) {
            float hp = __ldg(&var[1]);
            r.x = hp; r.y = -hp;
        }
        return r;
    }

    float mu0   = __ldg(&mu[0]);
    float mu1   = __ldg(&mu[1]);
    float var01 = __ldg(&var[1]);
    float c = var01 - 2.f * mu0 * mu1;

    if (i < 2u) {
        float s = (i == 0u) ? 1.f : -1.f;
        float* rr = &r.x;
        #pragma unroll
        for (int q = 0; q < 4; ++q) {
            unsigned int jj = j + (unsigned int)q;
            float vj = 0.f;                      // excludes j == prey / hunter
            if (jj >= 2u)
                vj = fmaf(__ldg(&mu[jj]), c,
                      fmaf(mu1, __ldg(&var[jj]),           // var[0, jj]
                           mu0 * __ldg(&var[N + jj])));    // var[1, jj]
            rr[q] = s * vj;
        }
        if (j == 0u)
            corner2x2(mu0, mu1, __ldg(&var[0]), var01, __ldg(&var[N + 1]),
                      i, &r.x, &r.y);
    } else {
        // j == 0, rows i >= 2: columns 0/1 hold +v[i], -v[i]
        float vi = fmaf(__ldg(&mu[i]), c,
                    fmaf(mu1, __ldg(&var[i]),              // var[0, i]
                         mu0 * __ldg(&var[N + i])));       // var[1, i]
        r.x = vi; r.y = -vi;
    }
    return r;
}

// Exact-grid kernel: grid * TPB * VPT == total4 (no bounds checks anywhere).
__global__ void __launch_bounds__(TPB)
eatrxn_fused_kernel(const float* __restrict__ mu,
                    const float* __restrict__ var,
                    float* __restrict__ out,
                    unsigned int N,
                    unsigned int shift,
                    unsigned int mask) {
    unsigned int base = blockIdx.x * (TPB * VPT) + threadIdx.x;
    float4* __restrict__ out4 = reinterpret_cast<float4*>(out);

    #pragma unroll
    for (unsigned int k = 0; k < VPT; ++k) {
        unsigned int t = base + k * TPB;
        unsigned int off = t << 2;          // element offset of this float4
        unsigned int m = off - N;           // wraps for off < N; guarded below
        unsigned int i = m >> shift;        // row within M
        unsigned int j = m & mask;          // col within M (float4 spans j..j+3)

        float4 r = make_float4(0.f, 0.f, 0.f, 0.f);
        if ((off < N) | (i < 2u) | (j == 0u))
            r = special_value(off, mu, var, N, i, j);
        __stcs(&out4[t], r);                // streaming: write-once, never re-read
    }
}

// ---------------- Generic fallback (any N / out_size) ----------------
__global__ void eatrxn_generic_kernel(const float* __restrict__ mu,
                                      const float* __restrict__ var,
                                      float* __restrict__ out,
                                      long long total,
                                      unsigned int N) {
    long long t = (long long)blockIdx.x * blockDim.x + threadIdx.x;
    if (t >= total) return;
    float r = 0.f;
    if (t < (long long)N) {
        if (t == 0) r = __ldg(&var[1]);
        else if (t == 1) r = -__ldg(&var[1]);
    } else {
        long long m = t - N;
        unsigned int i = (unsigned int)(m / N);
        unsigned int j = (unsigned int)(m - (long long)i * N);
        if (i < 2u || j < 2u) {
            float mu0 = __ldg(&mu[0]), mu1 = __ldg(&mu[1]);
            float var01 = __ldg(&var[1]);
            float c = var01 - 2.f * mu0 * mu1;
            if (i < 2u && j < 2u) {
                float x, y;
                corner2x2(mu0, mu1, __ldg(&var[0]), var01, __ldg(&var[N + 1]),
                          i, &x, &y);
                r = (j == 0u) ? x : y;
            } else if (i < 2u) {
                float vj = fmaf(__ldg(&mu[j]), c,
                            fmaf(mu1, __ldg(&var[j]), mu0 * __ldg(&var[N + j])));
                r = (i == 0u) ? vj : -vj;
            } else {
                float vi = fmaf(__ldg(&mu[i]), c,
                            fmaf(mu1, __ldg(&var[i]), mu0 * __ldg(&var[N + i])));
                r = (j == 0u) ? vi : -vi;
            }
        }
    }
    out[t] = r;
}

extern "C" void kernel_launch(void* const* d_in, const int* in_sizes, int n_in,
                              void* d_out, int out_size) {
    const float* mu  = (const float*)d_in[0];
    const float* var = (const float*)d_in[1];
    float* out = (float*)d_out;

    unsigned int N = (unsigned int)in_sizes[0];     // 8192
    long long expect = (long long)N + (long long)N * N;
    long long total4ll = expect / 4;
    unsigned int per_block = TPB * VPT;             // 1024

    bool pow2 = (N & (N - 1u)) == 0u;
    if (pow2 && (long long)out_size == expect &&
        (expect % 4) == 0 && (total4ll % per_block) == 0) {
        unsigned int shift = 0;
        while ((1u << shift) < N) ++shift;          // 13 for N=8192
        unsigned int mask = N - 1u;
        unsigned int blocks = (unsigned int)(total4ll / per_block);  // 16386
        eatrxn_fused_kernel<<<blocks, TPB>>>(mu, var, out, N, shift, mask);
    } else {
        long long total = out_size;
        long long blocks = (total + TPB - 1) / TPB;
        eatrxn_generic_kernel<<<(unsigned int)blocks, TPB>>>(mu, var, out, total, N);
    }
}

// round 14
// speedup vs baseline: 1.0202x; 1.0202x over previous
#include <cuda_runtime.h>
#include <cuda_bf16.h>

// Output layout: [muTE (N floats)] ++ [M (N*N floats, row-major)]
// h = 0 (hunter), p = 1 (prey). N = 8192 for this problem.
//
// M is zero except rows/cols 0 and 1:
//   row 0: +v[j], row 1: -v[j], col 0: +v[i], col 1: -v[i], 2x2 corner special.
//   v[j] = mu[j]*(var01 - 2*mu0*mu1) + mu1*var[0,j] + mu0*var[1,j], v[0]=v[1]=0
//   (var[:,0] == var[0,:] bitwise since var = 0.5*(a + a^T)).
// muTE[0] = hp, muTE[1] = -hp, hp = var[0,1]; rest zero.
//
// TERMINAL FORM — evidence from rounds 1-13:
// Seven structurally distinct implementations (plain STG, __stcs, row-block,
// exact-grid, driver cudaMemsetAsync, memset+fixup, L2-resident-tail split)
// all drain the 268.5 MB output at ~7.2 TB/s store-issue / ~5.6 TB/s DRAM
// in 36.7-37.9 us; identical code re-runs span +-1.0 us (noise floor).
// Issue% varied 4.7-36.9 with no duration effect; cache policy inert; L2
// replay-residency falsified; grid shape inert. Binding resource: HBM3e
// write-turnaround wall for a unique-address store stream; output bytes
// contractually fixed. This configuration holds both best kernel time
// (36.67 us) and best end-to-end (39.42 us).

#define TPB 256u
#define VPT 4u   // float4 slots per thread; TPB*VPT divides total4 exactly

__device__ __forceinline__ void corner2x2(float mu0, float mu1,
                                          float var00, float var01, float var11,
                                          unsigned int row, float* x, float* y) {
    float hp = var01;
    float n3_pph = -2.f * mu1 * mu1 * mu0 + 2.f * mu1 * var01 + mu0 * var11;
    float n3_hhp = -2.f * mu0 * mu0 * mu1 + 2.f * mu0 * var01 + mu1 * var00;
    float n3_hpp = -2.f * mu0 * mu1 * mu1 + mu0 * var11 + 2.f * mu1 * var01;
    float chp = -n3_hhp + n3_hpp - hp;
    if (row == 0u) { *x = 2.f * n3_hhp + hp; *y = chp; }
    else           { *x = chp;               *y = -2.f * n3_pph + hp; }
}

__device__ __noinline__ float4 special_value(unsigned int off,
                                             const float* __restrict__ mu,
                                             const float* __restrict__ var,
                                             unsigned int N,
                                             unsigned int i,
                                             unsigned int j) {
    float4 r = make_float4(0.f, 0.f, 0.f, 0.f);

    if (off < N) {
        if (off == 0u) {
            float hp = __ldg(&var[1]);
            r.x = hp; r.y = -hp;
        }
        return r;
    }

    float mu0   = __ldg(&mu[0]);
    float mu1   = __ldg(&mu[1]);
    float var01 = __ldg(&var[1]);
    float c = var01 - 2.f * mu0 * mu1;

    if (i < 2u) {
        float s = (i == 0u) ? 1.f : -1.f;
        float* rr = &r.x;
        #pragma unroll
        for (int q = 0; q < 4; ++q) {
            unsigned int jj = j + (unsigned int)q;
            float vj = 0.f;                      // excludes j == prey / hunter
            if (jj >= 2u)
                vj = fmaf(__ldg(&mu[jj]), c,
                      fmaf(mu1, __ldg(&var[jj]),           // var[0, jj]
                           mu0 * __ldg(&var[N + jj])));    // var[1, jj]
            rr[q] = s * vj;
        }
        if (j == 0u)
            corner2x2(mu0, mu1, __ldg(&var[0]), var01, __ldg(&var[N + 1]),
                      i, &r.x, &r.y);
    } else {
        // j == 0, rows i >= 2: columns 0/1 hold +v[i], -v[i]
        float vi = fmaf(__ldg(&mu[i]), c,
                    fmaf(mu1, __ldg(&var[i]),              // var[0, i]
                         mu0 * __ldg(&var[N + i])));       // var[1, i]
        r.x = vi; r.y = -vi;
    }
    return r;
}

// Exact-grid kernel: grid * TPB * VPT == total4 (no bounds checks anywhere).
__global__ void __launch_bounds__(TPB)
eatrxn_fused_kernel(const float* __restrict__ mu,
                    const float* __restrict__ var,
                    float* __restrict__ out,
                    unsigned int N,
                    unsigned int shift,
                    unsigned int mask) {
    unsigned int base = blockIdx.x * (TPB * VPT) + threadIdx.x;
    float4* __restrict__ out4 = reinterpret_cast<float4*>(out);

    #pragma unroll
    for (unsigned int k = 0; k < VPT; ++k) {
        unsigned int t = base + k * TPB;
        unsigned int off = t << 2;          // element offset of this float4
        unsigned int m = off - N;           // wraps for off < N; guarded below
        unsigned int i = m >> shift;        // row within M
        unsigned int j = m & mask;          // col within M (float4 spans j..j+3)

        float4 r = make_float4(0.f, 0.f, 0.f, 0.f);
        if ((off < N) | (i < 2u) | (j == 0u))
            r = special_value(off, mu, var, N, i, j);
        __stcs(&out4[t], r);                // streaming: write-once, never re-read
    }
}

// ---------------- Generic fallback (any N / out_size) ----------------
__global__ void eatrxn_generic_kernel(const float* __restrict__ mu,
                                      const float* __restrict__ var,
                                      float* __restrict__ out,
                                      long long total,
                                      unsigned int N) {
    long long t = (long long)blockIdx.x * blockDim.x + threadIdx.x;
    if (t >= total) return;
    float r = 0.f;
    if (t < (long long)N) {
        if (t == 0) r = __ldg(&var[1]);
        else if (t == 1) r = -__ldg(&var[1]);
    } else {
        long long m = t - N;
        unsigned int i = (unsigned int)(m / N);
        unsigned int j = (unsigned int)(m - (long long)i * N);
        if (i < 2u || j < 2u) {
            float mu0 = __ldg(&mu[0]), mu1 = __ldg(&mu[1]);
            float var01 = __ldg(&var[1]);
            float c = var01 - 2.f * mu0 * mu1;
            if (i < 2u && j < 2u) {
                float x, y;
                corner2x2(mu0, mu1, __ldg(&var[0]), var01, __ldg(&var[N + 1]),
                          i, &x, &y);
                r = (j == 0u) ? x : y;
            } else if (i < 2u) {
                float vj = fmaf(__ldg(&mu[j]), c,
                            fmaf(mu1, __ldg(&var[j]), mu0 * __ldg(&var[N + j])));
                r = (i == 0u) ? vj : -vj;
            } else {
                float vi = fmaf(__ldg(&mu[i]), c,
                            fmaf(mu1, __ldg(&var[i]), mu0 * __ldg(&var[N + i])));
                r = (j == 0u) ? vi : -vi;
            }
        }
    }
    out[t] = r;
}

extern "C" void kernel_launch(void* const* d_in, const int* in_sizes, int n_in,
                              void* d_out, int out_size) {
    const float* mu  = (const float*)d_in[0];
    const float* var = (const float*)d_in[1];
    float* out = (float*)d_out;

    unsigned int N = (unsigned int)in_sizes[0];     // 8192
    long long expect = (long long)N + (long long)N * N;
    long long total4ll = expect / 4;
    unsigned int per_block = TPB * VPT;             // 1024

    bool pow2 = (N & (N - 1u)) == 0u;
    if (pow2 && (long long)out_size == expect &&
        (expect % 4) == 0 && (total4ll % per_block) == 0) {
        unsigned int shift = 0;
        while ((1u << shift) < N) ++shift;          // 13 for N=8192
        unsigned int mask = N - 1u;
        unsigned int blocks = (unsigned int)(total4ll / per_block);  // 16386
        eatrxn_fused_kernel<<<blocks, TPB>>>(mu, var, out, N, shift, mask);
    } else {
        long long total = out_size;
        long long blocks = (total + TPB - 1) / TPB;
        eatrxn_generic_kernel<<<(unsigned int)blocks, TPB>>>(mu, var, out, total, N);
    }
}